// round 1
// baseline (speedup 1.0000x reference)
#include <cuda_runtime.h>

#define BATCH 2
#define SEQ   2048
#define DIM   2048
#define NH    16
#define NKV   4
#define HD    128
#define QDIM  (NH*HD)      // 2048
#define KVDIM (2*NKV*HD)   // 1024
#define ROWS  (BATCH*SEQ)  // 4096

// Scratch (allocation-free rule: __device__ globals)
__device__ float g_q [(size_t)ROWS*QDIM];   // 33.5 MB
__device__ float g_kv[(size_t)ROWS*KVDIM];  // 16.8 MB
__device__ float g_vo[(size_t)ROWS*QDIM];   // 33.5 MB

// ---------------------------------------------------------------------------
// SGEMM: C[M,N] = A[M,K] @ B[K,N] + bias[N]   (row-major, all dims %128==0)
// 128x128 tile, BK=8, 256 threads, 8x8 microtile
// ---------------------------------------------------------------------------
__global__ __launch_bounds__(256) void sgemm_bias(
    const float* __restrict__ A, const float* __restrict__ Bm,
    const float* __restrict__ bias, float* __restrict__ C,
    int M, int N, int K)
{
    __shared__ float As[8][128];
    __shared__ float Bs[8][128];

    const int tid = threadIdx.x;
    const int tx = tid & 15, ty = tid >> 4;
    const long brow0 = (long)blockIdx.y * 128;
    const int  bcol0 = blockIdx.x * 128;

    float acc[8][8];
#pragma unroll
    for (int i = 0; i < 8; i++)
#pragma unroll
        for (int j = 0; j < 8; j++) acc[i][j] = 0.f;

    const int arow = tid >> 1, acol = (tid & 1) << 2;   // 128 rows x 8 cols
    const int brw  = tid >> 5, bcl  = (tid & 31) << 2;  // 8 rows x 128 cols

    const float* Ap = A + (brow0 + arow) * (long)K + acol;
    const float* Bp = Bm + (long)brw * N + bcol0 + bcl;

    for (int kt = 0; kt < K; kt += 8) {
        float4 a4 = *(const float4*)(Ap + kt);
        As[acol+0][arow] = a4.x; As[acol+1][arow] = a4.y;
        As[acol+2][arow] = a4.z; As[acol+3][arow] = a4.w;
        float4 b4 = *(const float4*)(Bp + (long)kt * N);
        *(float4*)&Bs[brw][bcl] = b4;
        __syncthreads();

#pragma unroll
        for (int kk = 0; kk < 8; kk++) {
            float af[8], bf[8];
            *(float4*)(af)   = *(const float4*)&As[kk][ty*8];
            *(float4*)(af+4) = *(const float4*)&As[kk][ty*8+4];
            *(float4*)(bf)   = *(const float4*)&Bs[kk][tx*8];
            *(float4*)(bf+4) = *(const float4*)&Bs[kk][tx*8+4];
#pragma unroll
            for (int i = 0; i < 8; i++)
#pragma unroll
                for (int j = 0; j < 8; j++) acc[i][j] += af[i]*bf[j];
        }
        __syncthreads();
    }

#pragma unroll
    for (int i = 0; i < 8; i++) {
        long r = brow0 + ty*8 + i;
#pragma unroll
        for (int j = 0; j < 8; j += 4) {
            int c = bcol0 + tx*8 + j;
            float4 o;
            o.x = acc[i][j+0] + bias[c+0];
            o.y = acc[i][j+1] + bias[c+1];
            o.z = acc[i][j+2] + bias[c+2];
            o.w = acc[i][j+3] + bias[c+3];
            *(float4*)(C + r*N + c) = o;
        }
    }
}

// ---------------------------------------------------------------------------
// RoPE applied in-place to Q (16 heads) and K part of KV (4 heads)
// ---------------------------------------------------------------------------
__global__ void rope_kernel(float* __restrict__ q, float* __restrict__ kv,
                            const float* __restrict__ cs, const float* __restrict__ sn)
{
    const int row = blockIdx.x;       // b*SEQ + s
    const int s = row & (SEQ-1);
    for (int t = threadIdx.x; t < (NH+NKV)*64; t += blockDim.x) {
        int head = t >> 6, d = t & 63;
        float c  = cs[s*64 + d];
        float si = sn[s*64 + d];
        float* p1;
        if (head < NH) p1 = q  + (size_t)row*QDIM  + head*HD + d;
        else           p1 = kv + (size_t)row*KVDIM + (head-NH)*HD + d;
        float* p2 = p1 + 64;
        float x1 = *p1, x2 = *p2;
        *p1 = x1*c - x2*si;
        *p2 = x1*si + x2*c;
    }
}

// ---------------------------------------------------------------------------
// Flash attention fp32: block = (q-tile of 64, head, batch), 256 threads
// smem: Qs[128][64] Ks[128][64] Vs[64][128] Ps[64][65]  = ~112 KB dynamic
// thread (ty,tx): S-frag 4 rows x 4 cols, O-frag 4 rows x 8 cols
// ---------------------------------------------------------------------------
#define FA_SMEM ((128*64 + 128*64 + 64*128 + 64*65) * 4)

__global__ __launch_bounds__(256) void flash_attn(
    const float* __restrict__ Q, const float* __restrict__ KV,
    float* __restrict__ O, const int* __restrict__ causal_p)
{
    extern __shared__ float sm[];
    float* Qs = sm;                 // [128][64]  Qs[d*64 + r]  (transposed)
    float* Ks = Qs + 128*64;        // [128][64]  (transposed)
    float* Vs = Ks + 128*64;        // [64][128]
    float* Ps = Vs + 64*128;        // [64][65]

    const int causal = *causal_p;
    const int qt = blockIdx.x, h = blockIdx.y, b = blockIdx.z;
    const int kh = h >> 2;          // GQA: rep = 4
    const int q0 = qt << 6;
    const int tid = threadIdx.x;
    const int tx = tid & 15, ty = tid >> 4;
    const float scale = 0.08838834764831845f;  // 1/sqrt(128)

    // load + transpose + pre-scale Q tile
    const float* Qb = Q + ((size_t)(b*SEQ + q0))*QDIM + h*HD;
    for (int i = tid; i < 64*32; i += 256) {
        int r = i >> 5, d4 = (i & 31) << 2;
        float4 v = *(const float4*)(Qb + (size_t)r*QDIM + d4);
        Qs[(d4+0)*64 + r] = v.x*scale; Qs[(d4+1)*64 + r] = v.y*scale;
        Qs[(d4+2)*64 + r] = v.z*scale; Qs[(d4+3)*64 + r] = v.w*scale;
    }

    float m[4], l[4], o[4][8];
#pragma unroll
    for (int i = 0; i < 4; i++) {
        m[i] = -1e30f; l[i] = 0.f;
#pragma unroll
        for (int j = 0; j < 8; j++) o[i][j] = 0.f;
    }

    const int nkt = causal ? (qt + 1) : (SEQ >> 6);
    const float* Kb = KV + (size_t)(b*SEQ)*KVDIM + kh*HD;

    for (int kt = 0; kt < nkt; kt++) {
        __syncthreads();   // protects Qs (1st iter) and Ks/Vs/Ps reuse
        // load K (transposed) + V tiles
        for (int i = tid; i < 64*32; i += 256) {
            int r = i >> 5, d4 = (i & 31) << 2;
            const float* kp = Kb + (size_t)((kt<<6) + r)*KVDIM + d4;
            float4 k4 = *(const float4*)kp;
            Ks[(d4+0)*64 + r] = k4.x; Ks[(d4+1)*64 + r] = k4.y;
            Ks[(d4+2)*64 + r] = k4.z; Ks[(d4+3)*64 + r] = k4.w;
            float4 v4 = *(const float4*)(kp + NKV*HD);   // V at +512 cols
            *(float4*)&Vs[r*128 + d4] = v4;
        }
        __syncthreads();

        // S = Q K^T  (64x64, 4x4 per thread)
        float sacc[4][4];
#pragma unroll
        for (int i = 0; i < 4; i++)
#pragma unroll
            for (int j = 0; j < 4; j++) sacc[i][j] = 0.f;

#pragma unroll 8
        for (int d = 0; d < 128; d++) {
            float af[4], bf[4];
            *(float4*)af = *(const float4*)&Qs[d*64 + ty*4];
            *(float4*)bf = *(const float4*)&Ks[d*64 + tx*4];
#pragma unroll
            for (int i = 0; i < 4; i++)
#pragma unroll
                for (int j = 0; j < 4; j++) sacc[i][j] += af[i]*bf[j];
        }

        const bool diag = (causal && kt == qt);
#pragma unroll
        for (int i = 0; i < 4; i++) {
            const int qg = q0 + ty*4 + i;
            if (diag) {
#pragma unroll
                for (int j = 0; j < 4; j++) {
                    int kg = (kt << 6) + tx*4 + j;
                    if (kg > qg) sacc[i][j] = -1e30f;
                }
            }
            float rm = fmaxf(fmaxf(sacc[i][0], sacc[i][1]),
                             fmaxf(sacc[i][2], sacc[i][3]));
            rm = fmaxf(rm, __shfl_xor_sync(0xffffffffu, rm, 8));
            rm = fmaxf(rm, __shfl_xor_sync(0xffffffffu, rm, 4));
            rm = fmaxf(rm, __shfl_xor_sync(0xffffffffu, rm, 2));
            rm = fmaxf(rm, __shfl_xor_sync(0xffffffffu, rm, 1));
            float mnew   = fmaxf(m[i], rm);
            float factor = __expf(m[i] - mnew);
            float rs = 0.f;
#pragma unroll
            for (int j = 0; j < 4; j++) {
                float p = __expf(sacc[i][j] - mnew);
                Ps[(ty*4+i)*65 + tx*4 + j] = p;
                rs += p;
            }
            rs += __shfl_xor_sync(0xffffffffu, rs, 8);
            rs += __shfl_xor_sync(0xffffffffu, rs, 4);
            rs += __shfl_xor_sync(0xffffffffu, rs, 2);
            rs += __shfl_xor_sync(0xffffffffu, rs, 1);
            l[i] = l[i]*factor + rs;
            m[i] = mnew;
#pragma unroll
            for (int j = 0; j < 8; j++) o[i][j] *= factor;
        }
        __syncthreads();

        // O += P V  (P from smem, 4 rows x 8 cols per thread)
#pragma unroll 4
        for (int k = 0; k < 64; k++) {
            float vf[8];
            *(float4*)(vf)   = *(const float4*)&Vs[k*128 + tx*8];
            *(float4*)(vf+4) = *(const float4*)&Vs[k*128 + tx*8 + 4];
#pragma unroll
            for (int i = 0; i < 4; i++) {
                float p = Ps[(ty*4+i)*65 + k];
#pragma unroll
                for (int j = 0; j < 8; j++) o[i][j] += p*vf[j];
            }
        }
    }

    // epilogue: O /= l, write to vo
    float* Ob = O + ((size_t)(b*SEQ + q0))*QDIM + h*HD;
#pragma unroll
    for (int i = 0; i < 4; i++) {
        int r = ty*4 + i;
        float inv = 1.0f / l[i];
        float of[8];
#pragma unroll
        for (int j = 0; j < 8; j++) of[j] = o[i][j]*inv;
        *(float4*)(Ob + (size_t)r*QDIM + tx*8)     = *(float4*)(of);
        *(float4*)(Ob + (size_t)r*QDIM + tx*8 + 4) = *(float4*)(of+4);
    }
}

// ---------------------------------------------------------------------------
extern "C" void kernel_launch(void* const* d_in, const int* in_sizes, int n_in,
                              void* d_out, int out_size)
{
    const float* x    = (const float*)d_in[0];
    const float* cosp = (const float*)d_in[1];
    const float* sinp = (const float*)d_in[2];
    const float* Wq   = (const float*)d_in[3];
    const float* bq   = (const float*)d_in[4];
    const float* Wkv  = (const float*)d_in[5];
    const float* bkv  = (const float*)d_in[6];
    const float* Wo   = (const float*)d_in[7];
    const float* bo   = (const float*)d_in[8];
    const int*   causal = (const int*)d_in[9];
    float* out = (float*)d_out;

    float *q, *kv, *vo;
    cudaGetSymbolAddress((void**)&q,  g_q);
    cudaGetSymbolAddress((void**)&kv, g_kv);
    cudaGetSymbolAddress((void**)&vo, g_vo);

    cudaFuncSetAttribute(flash_attn,
                         cudaFuncAttributeMaxDynamicSharedMemorySize, FA_SMEM);

    dim3 blk(256);
    // Q = x@Wq + bq ; KV = x@Wkv + bkv
    sgemm_bias<<<dim3(QDIM/128,  ROWS/128), blk>>>(x, Wq,  bq,  q,  ROWS, QDIM,  DIM);
    sgemm_bias<<<dim3(KVDIM/128, ROWS/128), blk>>>(x, Wkv, bkv, kv, ROWS, KVDIM, DIM);
    // RoPE in-place on q and k
    rope_kernel<<<ROWS, 256>>>(q, kv, cosp, sinp);
    // attention -> vo
    flash_attn<<<dim3(SEQ/64, NH, BATCH), blk, FA_SMEM>>>(q, kv, vo, causal);
    // out = vo@Wo + bo
    sgemm_bias<<<dim3(DIM/128, ROWS/128), blk>>>(vo, Wo, bo, out, ROWS, DIM, DIM);
}